// round 3
// baseline (speedup 1.0000x reference)
#include <cuda_runtime.h>
#include <cuda_bf16.h>
#include <math.h>
#include <stdint.h>

#define N_NODES   8192
#define C_IN      256
#define C_OUT     128
#define NEG_SLOPE 0.2f
#define MAX_DEG   128

#define GEMM_BLOCKS 128          // 8192 / BM
#define SCAN_BLOCKS 2048
#define BM 64
#define BK 16

// scan pipeline: 4 stages x 8KB chunks (512 uint4 each), 16 chunks per block
#define STAGES      4
#define CHUNK_U4    512          // 8KB / 16B
#define NCHUNK      16           // per block: 16 * 8KB = 128KB
#define BLOCK_U4    (CHUNK_U4 * NCHUNK)   // 8192 uint4 per block

// -------- scratch (__device__ globals; zero-initialized at module load) ----
__device__ float g_h[N_NODES * C_OUT];      // 4 MB, h = x @ W
__device__ float g_asrc[N_NODES];
__device__ float g_adst[N_NODES];
__device__ int   g_cnt[N_NODES];            // per-column degree (excl. self)
__device__ int   g_list[N_NODES * MAX_DEG]; // 4 MB, CSC row lists

// ---------------- small PTX helpers ----------------
__device__ __forceinline__ uint32_t smem_u32(const void* p) {
    uint32_t a;
    asm("{ .reg .u64 t; cvta.to.shared.u64 t, %1; cvt.u32.u64 %0, t; }"
        : "=r"(a) : "l"(p));
    return a;
}
__device__ __forceinline__ void mbar_init(uint32_t mbar, uint32_t count) {
    asm volatile("mbarrier.init.shared.b64 [%0], %1;" :: "r"(mbar), "r"(count) : "memory");
}
__device__ __forceinline__ void mbar_expect_tx(uint32_t mbar, uint32_t bytes) {
    asm volatile("mbarrier.arrive.expect_tx.shared.b64 _, [%0], %1;"
                 :: "r"(mbar), "r"(bytes) : "memory");
}
__device__ __forceinline__ void bulk_g2s(uint32_t dst_smem, const void* src, uint32_t bytes,
                                         uint32_t mbar) {
    asm volatile(
        "cp.async.bulk.shared::cta.global.mbarrier::complete_tx::bytes [%0], [%1], %2, [%3];"
        :: "r"(dst_smem), "l"(src), "r"(bytes), "r"(mbar) : "memory");
}
__device__ __forceinline__ void mbar_wait(uint32_t mbar, uint32_t parity) {
    asm volatile(
        "{\n\t"
        ".reg .pred P;\n\t"
        "WL_%=:\n\t"
        "mbarrier.try_wait.parity.shared.b64 P, [%0], %1;\n\t"
        "@P bra.uni WD_%=;\n\t"
        "bra.uni WL_%=;\n\t"
        "WD_%=:\n\t"
        "}"
        :: "r"(mbar), "r"(parity) : "memory");
}

// ---------------------------------------------------------------------
// Fused front kernel.
//  blocks [0, GEMM_BLOCKS):            h = x@W + attention-score epilogue
//  blocks [GEMM_BLOCKS, +SCAN_BLOCKS): stream adj once via cp.async.bulk
//                                      pipeline, build CSC neighbor lists
// g_cnt is zeroed by the previous aggregate launch (zero-init at load).
// ---------------------------------------------------------------------
__global__ __launch_bounds__(256) void fused_front_kernel(
    const float* __restrict__ x, const float* __restrict__ W,
    const float* __restrict__ adj,
    const float* __restrict__ att_src, const float* __restrict__ att_dst) {

    __shared__ union SmemU {
        struct { float xs[BK][BM]; float ws[BK][C_OUT]; } g;             // 12 KB
        struct { alignas(128) uint4 buf[STAGES][CHUNK_U4];               // 32 KB
                 alignas(8) unsigned long long mbar[STAGES]; } s;
    } su;

    if (blockIdx.x < GEMM_BLOCKS) {
        // ================= GEMM + attention epilogue =================
        float (*xs)[BM]    = su.g.xs;
        float (*ws)[C_OUT] = su.g.ws;

        int tid  = threadIdx.x;
        int row0 = blockIdx.x * BM;
        int tx = tid & 31;   // channel group: c = tx*4
        int ty = tid >> 5;   // row group: r0 = ty*8  (warp == fixed ty)

        float acc[8][4];
#pragma unroll
        for (int r = 0; r < 8; r++)
#pragma unroll
            for (int c = 0; c < 4; c++) acc[r][c] = 0.0f;

        for (int k0 = 0; k0 < C_IN; k0 += BK) {
            {
                int r  = tid >> 2;
                int kk = (tid & 3) * 4;
                float4 v = *reinterpret_cast<const float4*>(
                    &x[(row0 + r) * C_IN + k0 + kk]);
                xs[kk + 0][r] = v.x; xs[kk + 1][r] = v.y;
                xs[kk + 2][r] = v.z; xs[kk + 3][r] = v.w;
            }
            {
                int kk = tid >> 5;
                int c  = (tid & 31) * 4;
                *reinterpret_cast<float4*>(&ws[kk][c]) =
                    *reinterpret_cast<const float4*>(&W[(k0 + kk) * C_OUT + c]);
                *reinterpret_cast<float4*>(&ws[kk + 8][c]) =
                    *reinterpret_cast<const float4*>(&W[(k0 + kk + 8) * C_OUT + c]);
            }
            __syncthreads();
#pragma unroll
            for (int kk = 0; kk < BK; kk++) {
                float4 b = *reinterpret_cast<const float4*>(&ws[kk][tx * 4]);
#pragma unroll
                for (int r = 0; r < 8; r++) {
                    float a = xs[kk][ty * 8 + r];
                    acc[r][0] += a * b.x;
                    acc[r][1] += a * b.y;
                    acc[r][2] += a * b.z;
                    acc[r][3] += a * b.w;
                }
            }
            __syncthreads();
        }

        float4 as = *reinterpret_cast<const float4*>(&att_src[tx * 4]);
        float4 ad = *reinterpret_cast<const float4*>(&att_dst[tx * 4]);

#pragma unroll
        for (int r = 0; r < 8; r++) {
            int row = row0 + ty * 8 + r;
            float4 v = make_float4(acc[r][0], acc[r][1], acc[r][2], acc[r][3]);
            *reinterpret_cast<float4*>(&g_h[row * C_OUT + tx * 4]) = v;

            float s = v.x * as.x + v.y * as.y + v.z * as.z + v.w * as.w;
            float d = v.x * ad.x + v.y * ad.y + v.z * ad.z + v.w * ad.w;
#pragma unroll
            for (int o = 16; o > 0; o >>= 1) {
                s += __shfl_xor_sync(0xFFFFFFFFu, s, o);
                d += __shfl_xor_sync(0xFFFFFFFFu, d, o);
            }
            if (tx == 0) { g_asrc[row] = s; g_adst[row] = d; }
        }
    } else {
        // ============ adjacency scan: bulk-async smem pipeline ============
        const int sb   = blockIdx.x - GEMM_BLOCKS;
        const int tid  = threadIdx.x;
        const int base_q_blk = sb * BLOCK_U4;             // uint4 index base
        const uint4* adj4 = reinterpret_cast<const uint4*>(adj);

        uint32_t mb[STAGES];
#pragma unroll
        for (int st = 0; st < STAGES; st++) mb[st] = smem_u32(&su.s.mbar[st]);

        if (tid == 0) {
#pragma unroll
            for (int st = 0; st < STAGES; st++) mbar_init(mb[st], 1);
        }
        __syncthreads();

        if (tid == 0) {
#pragma unroll
            for (int c = 0; c < STAGES; c++) {
                mbar_expect_tx(mb[c], CHUNK_U4 * 16);
                bulk_g2s(smem_u32(&su.s.buf[c][0]),
                         &adj4[base_q_blk + c * CHUNK_U4], CHUNK_U4 * 16, mb[c]);
            }
        }

        for (int c = 0; c < NCHUNK; c++) {
            int st = c & (STAGES - 1);
            mbar_wait(mb[st], (c >> 2) & 1);

            int chunk_q = base_q_blk + c * CHUNK_U4;
#pragma unroll
            for (int u = 0; u < 2; u++) {
                int local = tid + u * 256;
                uint4 v = su.s.buf[st][local];
                if ((v.x | v.y | v.z | v.w) == 0u) continue;
                int Q  = chunk_q + local;
                int i  = Q >> 11;                 // row (2048 uint4 per row)
                int j0 = (Q & 2047) << 2;         // first column of the 4
                unsigned int b[4] = {v.x, v.y, v.z, v.w};
#pragma unroll
                for (int t = 0; t < 4; t++) {
                    if (b[t] != 0u) {
                        int jj = j0 + t;
                        if (jj != i) {            // diagonal handled in aggregate
                            int pos = atomicAdd(&g_cnt[jj], 1);
                            if (pos < MAX_DEG) g_list[jj * MAX_DEG + pos] = i;
                        }
                    }
                }
            }
            __syncthreads();   // everyone done reading stage st
            if (tid == 0 && c + STAGES < NCHUNK) {
                mbar_expect_tx(mb[st], CHUNK_U4 * 16);
                bulk_g2s(smem_u32(&su.s.buf[st][0]),
                         &adj4[base_q_blk + (c + STAGES) * CHUNK_U4],
                         CHUNK_U4 * 16, mb[st]);
            }
        }
    }
}

// ---------------------------------------------------------------------
// Aggregate: per-column softmax + gather, split accumulators for MLP.
// Resets g_cnt for the next graph replay.
// ---------------------------------------------------------------------
__global__ __launch_bounds__(128) void aggregate_kernel(
    const float* __restrict__ bias, float* __restrict__ out) {
    int j = blockIdx.x;
    int t = threadIdx.x;  // channel, 0..127

    __shared__ int   sidx[MAX_DEG];
    __shared__ float sew[MAX_DEG];

    int cnt = g_cnt[j];
    if (cnt > MAX_DEG) cnt = MAX_DEG;
    float adst_j = g_adst[j];

    if (t < cnt) {
        int i = g_list[j * MAX_DEG + t];
        sidx[t] = i;
        float z = g_asrc[i] + adst_j;
        z = (z > 0.0f) ? z : NEG_SLOPE * z;
        sew[t] = __expf(z);
    }
    __syncthreads();
    if (t == 0) g_cnt[j] = 0;   // reset for next graph replay

    // self-loop (reference SETS the diagonal to 1 -> always present)
    float zs = g_asrc[j] + adst_j;
    zs = (zs > 0.0f) ? zs : NEG_SLOPE * zs;
    float es = __expf(zs);

    float acc0 = es * g_h[j * C_OUT + t], acc1 = 0.0f;
    float sum0 = es, sum1 = 0.0f;

    int d = 0;
    for (; d + 4 <= cnt; d += 4) {
        int   i0 = sidx[d],   i1 = sidx[d+1], i2 = sidx[d+2], i3 = sidx[d+3];
        float e0 = sew[d],    e1 = sew[d+1],  e2 = sew[d+2],  e3 = sew[d+3];
        float h0 = g_h[i0 * C_OUT + t];
        float h1 = g_h[i1 * C_OUT + t];
        float h2 = g_h[i2 * C_OUT + t];
        float h3 = g_h[i3 * C_OUT + t];
        acc0 += e0 * h0; acc1 += e1 * h1;
        acc0 += e2 * h2; acc1 += e3 * h3;
        sum0 += e0 + e2; sum1 += e1 + e3;
    }
    for (; d < cnt; d++) {
        float e = sew[d];
        acc0 += e * g_h[sidx[d] * C_OUT + t];
        sum0 += e;
    }
    float acc = acc0 + acc1;
    float sum = sum0 + sum1;
    out[j * C_OUT + t] = acc / sum + bias[t];
}

// ---------------------------------------------------------------------
extern "C" void kernel_launch(void* const* d_in, const int* in_sizes, int n_in,
                              void* d_out, int out_size) {
    const float* x       = (const float*)d_in[0];
    const float* adj     = (const float*)d_in[1];
    const float* W       = (const float*)d_in[2];
    const float* att_src = (const float*)d_in[3];
    const float* att_dst = (const float*)d_in[4];
    const float* bias    = (const float*)d_in[5];
    float* out = (float*)d_out;

    fused_front_kernel<<<GEMM_BLOCKS + SCAN_BLOCKS, 256>>>(x, W, adj, att_src, att_dst);
    aggregate_kernel<<<N_NODES, C_OUT>>>(bias, out);
}

// round 4
// speedup vs baseline: 1.7050x; 1.7050x over previous
#include <cuda_runtime.h>
#include <cuda_bf16.h>
#include <math.h>
#include <stdint.h>

#define N_NODES   8192
#define C_IN      256
#define C_OUT     128
#define NEG_SLOPE 0.2f
#define MAX_DEG   128

#define BM 32
#define BK 16
#define GEMM_BLOCKS (N_NODES / BM)     // 256
#define SCAN_BLOCKS 2048

// -------- scratch (__device__ globals; zero-initialized at module load) ----
__device__ float g_h[N_NODES * C_OUT];      // 4 MB, h = x @ W
__device__ float g_asrc[N_NODES];
__device__ float g_adst[N_NODES];
__device__ int   g_cnt[N_NODES];            // per-column degree (excl. self)
__device__ int   g_list[N_NODES * MAX_DEG]; // 4 MB, CSC row lists

// ---------------------------------------------------------------------
// Fused front kernel, register-capped so the scan branch keeps 7 CTAs/SM
// (56 warps x 1KB of LDG.128 in flight = 56KB/SM >> 25KB latency-BW
// product -> HBM-saturating).
//  blocks [0, GEMM_BLOCKS):            h = x@W (4x4 micro-tile) + attn scores
//  blocks [GEMM_BLOCKS, +SCAN_BLOCKS): stream adj once, build CSC lists
// g_cnt is zeroed by the previous aggregate launch (zero-init at load).
// ---------------------------------------------------------------------
__global__ __launch_bounds__(256, 7) void fused_front_kernel(
    const float* __restrict__ x, const float* __restrict__ W,
    const float* __restrict__ adj,
    const float* __restrict__ att_src, const float* __restrict__ att_dst) {

    if (blockIdx.x >= GEMM_BLOCKS) {
        // ============ adjacency scan: batch-2 LDG.128 stream ============
        const uint4* a4 = reinterpret_cast<const uint4*>(adj);
        const int tid0   = (blockIdx.x - GEMM_BLOCKS) * 256 + threadIdx.x;
        const int stride = SCAN_BLOCKS * 256;           // 524288
        const int total4 = (N_NODES / 4) * N_NODES;     // 16777216

        for (int q = tid0; q < total4; q += 2 * stride) {
            // two independent in-flight loads per warp
            uint4 v0 = __ldcs(&a4[q]);
            uint4 v1 = __ldcs(&a4[q + stride]);
#pragma unroll
            for (int u = 0; u < 2; u++) {
                uint4 v = (u == 0) ? v0 : v1;
                if ((v.x | v.y | v.z | v.w) == 0u) continue;
                int Q  = q + u * stride;
                int i  = Q >> 11;                 // row (2048 uint4 per row)
                int j0 = (Q & 2047) << 2;         // first column of the 4
                unsigned int b[4] = {v.x, v.y, v.z, v.w};
#pragma unroll
                for (int t = 0; t < 4; t++) {
                    if (b[t] != 0u) {
                        int jj = j0 + t;
                        if (jj != i) {            // diagonal handled in aggregate
                            int pos = atomicAdd(&g_cnt[jj], 1);
                            if (pos < MAX_DEG) g_list[jj * MAX_DEG + pos] = i;
                        }
                    }
                }
            }
        }
        return;
    }

    // ================= GEMM (BM=32, 4x4 micro-tile) + attention =================
    __shared__ float xs[BK][BM];       // 2 KB
    __shared__ float ws[BK][C_OUT];    // 8 KB

    int tid  = threadIdx.x;
    int row0 = blockIdx.x * BM;
    int tx = tid & 31;   // channel group: c = tx*4
    int ty = tid >> 5;   // row group: rows ty*4 .. ty*4+3 (warp == fixed ty)

    float acc[4][4];
#pragma unroll
    for (int r = 0; r < 4; r++)
#pragma unroll
        for (int c = 0; c < 4; c++) acc[r][c] = 0.0f;

    for (int k0 = 0; k0 < C_IN; k0 += BK) {
        {   // x tile: 32 rows x 16 k, one float2 per thread
            int r  = tid >> 3;          // 0..31
            int kk = (tid & 7) * 2;     // 0,2,..,14
            float2 v = *reinterpret_cast<const float2*>(
                &x[(row0 + r) * C_IN + k0 + kk]);
            xs[kk + 0][r] = v.x; xs[kk + 1][r] = v.y;
        }
        {   // W tile: 16 k x 128 c, two float4 per thread
            int kk = tid >> 5;              // 0..7
            int c  = (tid & 31) * 4;
            *reinterpret_cast<float4*>(&ws[kk][c]) =
                *reinterpret_cast<const float4*>(&W[(k0 + kk) * C_OUT + c]);
            *reinterpret_cast<float4*>(&ws[kk + 8][c]) =
                *reinterpret_cast<const float4*>(&W[(k0 + kk + 8) * C_OUT + c]);
        }
        __syncthreads();
#pragma unroll
        for (int kk = 0; kk < BK; kk++) {
            float4 b = *reinterpret_cast<const float4*>(&ws[kk][tx * 4]);
#pragma unroll
            for (int r = 0; r < 4; r++) {
                float a = xs[kk][ty * 4 + r];
                acc[r][0] += a * b.x;
                acc[r][1] += a * b.y;
                acc[r][2] += a * b.z;
                acc[r][3] += a * b.w;
            }
        }
        __syncthreads();
    }

    float4 as = *reinterpret_cast<const float4*>(&att_src[tx * 4]);
    float4 ad = *reinterpret_cast<const float4*>(&att_dst[tx * 4]);

#pragma unroll
    for (int r = 0; r < 4; r++) {
        int row = row0 + ty * 4 + r;
        float4 v = make_float4(acc[r][0], acc[r][1], acc[r][2], acc[r][3]);
        *reinterpret_cast<float4*>(&g_h[row * C_OUT + tx * 4]) = v;

        float s = v.x * as.x + v.y * as.y + v.z * as.z + v.w * as.w;
        float d = v.x * ad.x + v.y * ad.y + v.z * ad.z + v.w * ad.w;
#pragma unroll
        for (int o = 16; o > 0; o >>= 1) {
            s += __shfl_xor_sync(0xFFFFFFFFu, s, o);
            d += __shfl_xor_sync(0xFFFFFFFFu, d, o);
        }
        if (tx == 0) { g_asrc[row] = s; g_adst[row] = d; }
    }
}

// ---------------------------------------------------------------------
// Aggregate: 2 columns per 128-thread block; 64 threads/column with
// float2 gathers (half the per-byte instruction count of the 1-col
// version). Dual accumulators break the FADD dependency chains.
// Resets g_cnt for the next graph replay.
// ---------------------------------------------------------------------
__global__ __launch_bounds__(128) void aggregate_kernel(
    const float* __restrict__ bias, float* __restrict__ out) {
    int t  = threadIdx.x;          // 0..127
    int c  = t >> 6;               // column slot 0/1
    int l  = t & 63;               // lane within column
    int j  = blockIdx.x * 2 + c;

    __shared__ int   sidx[2][MAX_DEG];
    __shared__ float sew[2][MAX_DEG];

    int cnt = g_cnt[j];
    if (cnt > MAX_DEG) cnt = MAX_DEG;
    float adst_j = g_adst[j];

    for (int d = l; d < cnt; d += 64) {
        int i = g_list[j * MAX_DEG + d];
        sidx[c][d] = i;
        float z = g_asrc[i] + adst_j;
        z = (z > 0.0f) ? z : NEG_SLOPE * z;
        sew[c][d] = __expf(z);
    }
    __syncthreads();
    if (l == 0) g_cnt[j] = 0;   // reset for next graph replay

    // self-loop (reference SETS the diagonal to 1 -> always present)
    float zs = g_asrc[j] + adst_j;
    zs = (zs > 0.0f) ? zs : NEG_SLOPE * zs;
    float es = __expf(zs);

    float2 hj = *reinterpret_cast<const float2*>(&g_h[j * C_OUT + l * 2]);
    float ax0 = es * hj.x, ay0 = es * hj.y;
    float ax1 = 0.0f,      ay1 = 0.0f;
    float sum0 = es, sum1 = 0.0f;

    int d = 0;
    for (; d + 4 <= cnt; d += 4) {
        int   i0 = sidx[c][d],   i1 = sidx[c][d+1], i2 = sidx[c][d+2], i3 = sidx[c][d+3];
        float e0 = sew[c][d],    e1 = sew[c][d+1],  e2 = sew[c][d+2],  e3 = sew[c][d+3];
        float2 h0 = *reinterpret_cast<const float2*>(&g_h[i0 * C_OUT + l * 2]);
        float2 h1 = *reinterpret_cast<const float2*>(&g_h[i1 * C_OUT + l * 2]);
        float2 h2 = *reinterpret_cast<const float2*>(&g_h[i2 * C_OUT + l * 2]);
        float2 h3 = *reinterpret_cast<const float2*>(&g_h[i3 * C_OUT + l * 2]);
        ax0 += e0 * h0.x; ay0 += e0 * h0.y;
        ax1 += e1 * h1.x; ay1 += e1 * h1.y;
        ax0 += e2 * h2.x; ay0 += e2 * h2.y;
        ax1 += e3 * h3.x; ay1 += e3 * h3.y;
        sum0 += e0 + e2;  sum1 += e1 + e3;
    }
    for (; d < cnt; d++) {
        float e = sew[c][d];
        float2 hv = *reinterpret_cast<const float2*>(&g_h[sidx[c][d] * C_OUT + l * 2]);
        ax0 += e * hv.x; ay0 += e * hv.y;
        sum0 += e;
    }
    float inv = 1.0f / (sum0 + sum1);
    float2 bv = *reinterpret_cast<const float2*>(&bias[l * 2]);
    float2 o;
    o.x = (ax0 + ax1) * inv + bv.x;
    o.y = (ay0 + ay1) * inv + bv.y;
    *reinterpret_cast<float2*>(&out[j * C_OUT + l * 2]) = o;
}

// ---------------------------------------------------------------------
extern "C" void kernel_launch(void* const* d_in, const int* in_sizes, int n_in,
                              void* d_out, int out_size) {
    const float* x       = (const float*)d_in[0];
    const float* adj     = (const float*)d_in[1];
    const float* W       = (const float*)d_in[2];
    const float* att_src = (const float*)d_in[3];
    const float* att_dst = (const float*)d_in[4];
    const float* bias    = (const float*)d_in[5];
    float* out = (float*)d_out;

    fused_front_kernel<<<GEMM_BLOCKS + SCAN_BLOCKS, 256>>>(x, W, adj, att_src, att_dst);
    aggregate_kernel<<<N_NODES / 2, 128>>>(bias, out);
}

// round 5
// speedup vs baseline: 1.7499x; 1.0263x over previous
#include <cuda_runtime.h>
#include <cuda_bf16.h>
#include <math.h>
#include <stdint.h>

#define N_NODES   8192
#define C_IN      256
#define C_OUT     128
#define NEG_SLOPE 0.2f
#define MAX_DEG   128

#define BM 32
#define BK 16
#define GEMM_BLOCKS (N_NODES / BM)     // 256
#define SCAN_BLOCKS 2048

// -------- scratch (__device__ globals; zero-initialized at module load) ----
__device__ float g_h[N_NODES * C_OUT];      // 4 MB, h = x @ W
__device__ float g_asrc[N_NODES];
__device__ float g_adst[N_NODES];
__device__ int   g_cnt[N_NODES];            // per-column degree (excl. self)
__device__ int   g_list[N_NODES * MAX_DEG]; // 4 MB, CSC row lists

// ---------------------------------------------------------------------
// Fused front kernel.
//  blocks [0, GEMM_BLOCKS):            h = x@W (4x4 micro-tile) + attn scores
//  blocks [GEMM_BLOCKS, +SCAN_BLOCKS): stream adj once (batch-4 LDG.128),
//                                      build CSC neighbor lists
// launch_bounds(256,6): 42-reg budget -> no spill of the 4 in-flight uint4s;
// 48 warps/SM x 2KB in flight = ~96KB/SM >> latency-BW product (~25KB).
// g_cnt is zeroed by the previous aggregate launch (zero-init at load).
// ---------------------------------------------------------------------
__global__ __launch_bounds__(256, 6) void fused_front_kernel(
    const float* __restrict__ x, const float* __restrict__ W,
    const float* __restrict__ adj,
    const float* __restrict__ att_src, const float* __restrict__ att_dst) {

    if (blockIdx.x >= GEMM_BLOCKS) {
        // ============ adjacency scan: batch-4 LDG.128 stream ============
        const uint4* a4 = reinterpret_cast<const uint4*>(adj);
        const int tid0   = (blockIdx.x - GEMM_BLOCKS) * 256 + threadIdx.x;
        const int stride = SCAN_BLOCKS * 256;           // 524288
        const int total4 = (N_NODES / 4) * N_NODES;     // 16777216 = 32*stride

        for (int q = tid0; q < total4; q += 4 * stride) {
            // four independent in-flight loads per thread
            uint4 v0 = __ldcs(&a4[q]);
            uint4 v1 = __ldcs(&a4[q + stride]);
            uint4 v2 = __ldcs(&a4[q + 2 * stride]);
            uint4 v3 = __ldcs(&a4[q + 3 * stride]);
            uint4 vv[4] = {v0, v1, v2, v3};
#pragma unroll
            for (int u = 0; u < 4; u++) {
                uint4 v = vv[u];
                if ((v.x | v.y | v.z | v.w) == 0u) continue;
                int Q  = q + u * stride;
                int i  = Q >> 11;                 // row (2048 uint4 per row)
                int j0 = (Q & 2047) << 2;         // first column of the 4
                unsigned int b[4] = {v.x, v.y, v.z, v.w};
#pragma unroll
                for (int t = 0; t < 4; t++) {
                    if (b[t] != 0u) {
                        int jj = j0 + t;
                        if (jj != i) {            // diagonal handled in aggregate
                            int pos = atomicAdd(&g_cnt[jj], 1);
                            if (pos < MAX_DEG) g_list[jj * MAX_DEG + pos] = i;
                        }
                    }
                }
            }
        }
        return;
    }

    // ================= GEMM (BM=32, 4x4 micro-tile) + attention =================
    __shared__ float xs[BK][BM];       // 2 KB
    __shared__ float ws[BK][C_OUT];    // 8 KB

    int tid  = threadIdx.x;
    int row0 = blockIdx.x * BM;
    int tx = tid & 31;   // channel group: c = tx*4
    int ty = tid >> 5;   // row group: rows ty*4 .. ty*4+3 (warp == fixed ty)

    float acc[4][4];
#pragma unroll
    for (int r = 0; r < 4; r++)
#pragma unroll
        for (int c = 0; c < 4; c++) acc[r][c] = 0.0f;

    for (int k0 = 0; k0 < C_IN; k0 += BK) {
        {   // x tile: 32 rows x 16 k, one float2 per thread
            int r  = tid >> 3;          // 0..31
            int kk = (tid & 7) * 2;     // 0,2,..,14
            float2 v = *reinterpret_cast<const float2*>(
                &x[(row0 + r) * C_IN + k0 + kk]);
            xs[kk + 0][r] = v.x; xs[kk + 1][r] = v.y;
        }
        {   // W tile: 16 k x 128 c, two float4 per thread
            int kk = tid >> 5;              // 0..7
            int c  = (tid & 31) * 4;
            *reinterpret_cast<float4*>(&ws[kk][c]) =
                *reinterpret_cast<const float4*>(&W[(k0 + kk) * C_OUT + c]);
            *reinterpret_cast<float4*>(&ws[kk + 8][c]) =
                *reinterpret_cast<const float4*>(&W[(k0 + kk + 8) * C_OUT + c]);
        }
        __syncthreads();
#pragma unroll
        for (int kk = 0; kk < BK; kk++) {
            float4 b = *reinterpret_cast<const float4*>(&ws[kk][tx * 4]);
#pragma unroll
            for (int r = 0; r < 4; r++) {
                float a = xs[kk][ty * 4 + r];
                acc[r][0] += a * b.x;
                acc[r][1] += a * b.y;
                acc[r][2] += a * b.z;
                acc[r][3] += a * b.w;
            }
        }
        __syncthreads();
    }

    float4 as = *reinterpret_cast<const float4*>(&att_src[tx * 4]);
    float4 ad = *reinterpret_cast<const float4*>(&att_dst[tx * 4]);

#pragma unroll
    for (int r = 0; r < 4; r++) {
        int row = row0 + ty * 4 + r;
        float4 v = make_float4(acc[r][0], acc[r][1], acc[r][2], acc[r][3]);
        *reinterpret_cast<float4*>(&g_h[row * C_OUT + tx * 4]) = v;

        float s = v.x * as.x + v.y * as.y + v.z * as.z + v.w * as.w;
        float d = v.x * ad.x + v.y * ad.y + v.z * ad.z + v.w * ad.w;
#pragma unroll
        for (int o = 16; o > 0; o >>= 1) {
            s += __shfl_xor_sync(0xFFFFFFFFu, s, o);
            d += __shfl_xor_sync(0xFFFFFFFFu, d, o);
        }
        if (tx == 0) { g_asrc[row] = s; g_adst[row] = d; }
    }
}

// ---------------------------------------------------------------------
// Aggregate: one WARP per column. No smem, no block barriers.
// Lane d holds (idx, exp-weight) for edges d, d+32, d+64, d+96 in regs;
// per-edge broadcast via shfl; h-row gathers are per-lane float4
// (coalesced 512B), 4 independent in flight, dual float4 accumulators.
// Resets g_cnt for the next graph replay.
// ---------------------------------------------------------------------
#define FULLM 0xFFFFFFFFu
__global__ __launch_bounds__(256) void aggregate_kernel(
    const float* __restrict__ bias, float* __restrict__ out) {
    int lane = threadIdx.x & 31;
    int j    = blockIdx.x * 8 + (threadIdx.x >> 5);   // column

    int cnt = g_cnt[j];
    if (cnt > MAX_DEG) cnt = MAX_DEG;
    float adst_j = g_adst[j];

    int   idx[4];
    float ew[4];
#pragma unroll
    for (int u = 0; u < 4; u++) {
        int d = lane + u * 32;
        if (d < cnt) {
            int i = g_list[j * MAX_DEG + d];
            idx[u] = i;
            float z = g_asrc[i] + adst_j;
            z = (z > 0.0f) ? z : NEG_SLOPE * z;
            ew[u] = __expf(z);
        } else {
            idx[u] = 0;
            ew[u] = 0.0f;
        }
    }
    if (lane == 0) g_cnt[j] = 0;   // reset for next graph replay

    // self-loop (reference SETS the diagonal to 1 -> always present)
    float zs = g_asrc[j] + adst_j;
    zs = (zs > 0.0f) ? zs : NEG_SLOPE * zs;
    float es = __expf(zs);

    // column sum: warp reduce of all edge weights + self
    float psum = ew[0] + ew[1] + ew[2] + ew[3];
#pragma unroll
    for (int o = 16; o > 0; o >>= 1) psum += __shfl_xor_sync(FULLM, psum, o);
    float inv = 1.0f / (psum + es);

    const float4* hj4 = reinterpret_cast<const float4*>(&g_h[j * C_OUT]);
    float4 h0 = hj4[lane];
    float4 acc0 = make_float4(es * h0.x, es * h0.y, es * h0.z, es * h0.w);
    float4 acc1 = make_float4(0.f, 0.f, 0.f, 0.f);

#pragma unroll
    for (int u = 0; u < 4; u++) {
        int base = u * 32;
        if (base >= cnt) break;
        int m = cnt - base;
        if (m > 32) m = 32;
        int s = 0;
        for (; s + 4 <= m; s += 4) {
            float e0 = __shfl_sync(FULLM, ew[u], s);
            float e1 = __shfl_sync(FULLM, ew[u], s + 1);
            float e2 = __shfl_sync(FULLM, ew[u], s + 2);
            float e3 = __shfl_sync(FULLM, ew[u], s + 3);
            int i0 = __shfl_sync(FULLM, idx[u], s);
            int i1 = __shfl_sync(FULLM, idx[u], s + 1);
            int i2 = __shfl_sync(FULLM, idx[u], s + 2);
            int i3 = __shfl_sync(FULLM, idx[u], s + 3);
            float4 a = reinterpret_cast<const float4*>(&g_h[i0 * C_OUT])[lane];
            float4 b = reinterpret_cast<const float4*>(&g_h[i1 * C_OUT])[lane];
            float4 cc = reinterpret_cast<const float4*>(&g_h[i2 * C_OUT])[lane];
            float4 dd = reinterpret_cast<const float4*>(&g_h[i3 * C_OUT])[lane];
            acc0.x += e0 * a.x;  acc0.y += e0 * a.y;  acc0.z += e0 * a.z;  acc0.w += e0 * a.w;
            acc1.x += e1 * b.x;  acc1.y += e1 * b.y;  acc1.z += e1 * b.z;  acc1.w += e1 * b.w;
            acc0.x += e2 * cc.x; acc0.y += e2 * cc.y; acc0.z += e2 * cc.z; acc0.w += e2 * cc.w;
            acc1.x += e3 * dd.x; acc1.y += e3 * dd.y; acc1.z += e3 * dd.z; acc1.w += e3 * dd.w;
        }
        for (; s < m; s++) {
            float e = __shfl_sync(FULLM, ew[u], s);
            int  i  = __shfl_sync(FULLM, idx[u], s);
            float4 a = reinterpret_cast<const float4*>(&g_h[i * C_OUT])[lane];
            acc0.x += e * a.x; acc0.y += e * a.y; acc0.z += e * a.z; acc0.w += e * a.w;
        }
    }

    float4 bv = reinterpret_cast<const float4*>(bias)[lane];
    float4 o;
    o.x = (acc0.x + acc1.x) * inv + bv.x;
    o.y = (acc0.y + acc1.y) * inv + bv.y;
    o.z = (acc0.z + acc1.z) * inv + bv.z;
    o.w = (acc0.w + acc1.w) * inv + bv.w;
    reinterpret_cast<float4*>(&out[j * C_OUT])[lane] = o;
}

// ---------------------------------------------------------------------
extern "C" void kernel_launch(void* const* d_in, const int* in_sizes, int n_in,
                              void* d_out, int out_size) {
    const float* x       = (const float*)d_in[0];
    const float* adj     = (const float*)d_in[1];
    const float* W       = (const float*)d_in[2];
    const float* att_src = (const float*)d_in[3];
    const float* att_dst = (const float*)d_in[4];
    const float* bias    = (const float*)d_in[5];
    float* out = (float*)d_out;

    fused_front_kernel<<<GEMM_BLOCKS + SCAN_BLOCKS, 256>>>(x, W, adj, att_src, att_dst);
    aggregate_kernel<<<N_NODES / 8, 256>>>(bias, out);
}